// round 3
// baseline (speedup 1.0000x reference)
#include <cuda_runtime.h>
#include <math.h>

#define J 16
#define HID 128
#define ROWSB 131072            // 8192*16 rows per branch
#define EPSV 1e-5f

// ---------------- static device scratch (no runtime allocation) ----------------
__device__ float g_bufA[4 * ROWSB * HID];   // 256 MB
__device__ float g_bufB[4 * ROWSB * HID];   // 256 MB
__device__ float g_bufC[4 * ROWSB * HID];   // 256 MB
__device__ float g_merged[ROWSB * 12];
__device__ float g_partS[8192 * 128];
__device__ float g_partQ[8192 * 128];
__device__ float g_ssA[4 * 128];
__device__ float g_ssB[4 * 128];
__device__ float g_attO[15 * 256];          // softmax att, diag zeroed
__device__ float g_attD[15 * 16];           // softmax att diagonal

// Hardcoded H3.6M 16-joint adjacency (incl. self-loops), bit j of row i
__constant__ unsigned short MASKROW[16] = {
    0x0093, 0x0007, 0x000E, 0x000C, 0x0031, 0x0070, 0x0060, 0x0181,
    0x4B80, 0x0700, 0x0600, 0x1900, 0x3800, 0x3000, 0xC100, 0xC000};

// ---------------- attention softmax (15 layers x 16 rows) ----------------
__global__ void att_kernel(const float* __restrict__ e_in,
                           const float* __restrict__ e_cat,
                           const float* __restrict__ e_res,
                           const float* __restrict__ e_out,
                           float* __restrict__ attO, float* __restrict__ attD)
{
    int layer = blockIdx.x;      // 0=in, 1=cat, 2..9=res, 10..14=out
    int row = threadIdx.x;       // 16 threads
    const float* e;
    if (layer == 0)      e = e_in;
    else if (layer == 1) e = e_cat;
    else if (layer < 10) e = e_res + (layer - 2) * 256;
    else                 e = e_out + (layer - 10) * 256;

    unsigned m = MASKROW[row];
    float mx = -1e30f;
    for (int j = 0; j < 16; ++j)
        if ((m >> j) & 1) mx = fmaxf(mx, e[row * 16 + j]);
    float ex[16];
    float sum = 0.f;
    for (int j = 0; j < 16; ++j) {
        float v = ((m >> j) & 1) ? expf(e[row * 16 + j] - mx) : 0.f;
        ex[j] = v; sum += v;
    }
    float inv = 1.f / sum;
    for (int j = 0; j < 16; ++j)
        attO[layer * 256 + row * 16 + j] = (j == row) ? 0.f : ex[j] * inv;
    attD[layer * 16 + row] = ex[row] * inv;
}

// ---------------- main 128->128 graph conv (the hot kernel) ----------------
// Block: 64 rows (4 batches x 16 joints) x 128 cols, 256 threads, BK=16.
__global__ __launch_bounds__(256) void gconv128_kernel(
    const float* __restrict__ x, float* __restrict__ y,
    const float* __restrict__ W,        // [2][128][128]
    const float* __restrict__ attO, const float* __restrict__ attD,
    float* __restrict__ partS, float* __restrict__ partQ)
{
    __shared__ float xs[64][16];
    __shared__ float ms[64][16];
    __shared__ float w0s[16][128];
    __shared__ float w1s[16][128];
    __shared__ float aO[16][16];
    __shared__ float aD[16];

    int tid = threadIdx.x;
    int tx = tid & 31, ty = tid >> 5;
    ((float*)aO)[tid] = attO[tid];
    if (tid < 16) aD[tid] = attD[tid];

    int rowBase = blockIdx.x * 64;
    const float* xb = x + (long long)rowBase * HID;

    float acc[8][4];
#pragma unroll
    for (int r = 0; r < 8; ++r) { acc[r][0]=0.f; acc[r][1]=0.f; acc[r][2]=0.f; acc[r][3]=0.f; }

    for (int kt = 0; kt < 8; ++kt) {
        int k0 = kt * 16;
        // W tiles: 2 x 16x128 floats = 512 float4 per matrix
#pragma unroll
        for (int i = tid; i < 512; i += 256) {
            int kk = i >> 5, c4 = (i & 31) << 2;
            *(float4*)&w0s[kk][c4] = *(const float4*)&W[(k0 + kk) * HID + c4];
            *(float4*)&w1s[kk][c4] = *(const float4*)&W[16384 + (k0 + kk) * HID + c4];
        }
        // x tile: 64x16 floats = 256 float4
        {
            int r = tid >> 2, c4 = (tid & 3) << 2;
            *(float4*)&xs[r][c4] = *(const float4*)&xb[r * HID + k0 + c4];
        }
        __syncthreads();
        // mixed tile m[b,i,k] = sum_j attO[i][j] * x[b,j,k]
#pragma unroll
        for (int e = tid; e < 1024; e += 256) {
            int r = e >> 4, k = e & 15;
            int bl = r >> 4, ii = r & 15;
            float s = 0.f;
#pragma unroll
            for (int j = 0; j < 16; ++j) s += aO[ii][j] * xs[(bl << 4) + j][k];
            ms[r][k] = s;
        }
        __syncthreads();
        // diag scale in place
#pragma unroll
        for (int e = tid; e < 1024; e += 256) {
            int r = e >> 4, k = e & 15;
            xs[r][k] *= aD[r & 15];
        }
        __syncthreads();
#pragma unroll
        for (int k = 0; k < 16; ++k) {
            float4 w0 = *(float4*)&w0s[k][tx << 2];
            float4 w1 = *(float4*)&w1s[k][tx << 2];
#pragma unroll
            for (int rr = 0; rr < 8; ++rr) {
                float xd = xs[(ty << 3) + rr][k];
                float xm = ms[(ty << 3) + rr][k];
                acc[rr][0] += xd * w0.x + xm * w1.x;
                acc[rr][1] += xd * w0.y + xm * w1.y;
                acc[rr][2] += xd * w0.z + xm * w1.z;
                acc[rr][3] += xd * w0.w + xm * w1.w;
            }
        }
        __syncthreads();
    }
    // write y (no bias: it cancels in the following BatchNorm)
#pragma unroll
    for (int rr = 0; rr < 8; ++rr) {
        long long row = rowBase + (ty << 3) + rr;
        float4 v = make_float4(acc[rr][0], acc[rr][1], acc[rr][2], acc[rr][3]);
        *(float4*)&y[row * HID + (tx << 2)] = v;
    }
    // per-block BN partials (deterministic, no atomics)
    float ps[4] = {0.f,0.f,0.f,0.f}, pq[4] = {0.f,0.f,0.f,0.f};
#pragma unroll
    for (int rr = 0; rr < 8; ++rr)
#pragma unroll
        for (int c = 0; c < 4; ++c) { ps[c] += acc[rr][c]; pq[c] += acc[rr][c] * acc[rr][c]; }
    float* redS = &xs[0][0];   // 1024 floats
    float* redQ = &ms[0][0];   // 1024 floats
#pragma unroll
    for (int c = 0; c < 4; ++c) {
        redS[ty * 128 + (tx << 2) + c] = ps[c];
        redQ[ty * 128 + (tx << 2) + c] = pq[c];
    }
    __syncthreads();
    if (tid < 128) {
        float s = 0.f;
#pragma unroll
        for (int t = 0; t < 8; ++t) s += redS[t * 128 + tid];
        partS[(long long)blockIdx.x * 128 + tid] = s;
    } else {
        int c = tid - 128;
        float q = 0.f;
#pragma unroll
        for (int t = 0; t < 8; ++t) q += redQ[t * 128 + c];
        partQ[(long long)blockIdx.x * 128 + c] = q;
    }
}

// ---------------- small-Fin graph conv (Fin=2 input, Fin=12 cat) ----------------
__global__ __launch_bounds__(256) void gconv_small_kernel(
    const float* __restrict__ x0, const float* __restrict__ x1p,
    const float* __restrict__ x2p, const float* __restrict__ x3p,
    int fin,
    const float* __restrict__ W,        // [2][fin][128]
    const float* __restrict__ attO, const float* __restrict__ attD,
    float* __restrict__ y, float* __restrict__ partS, float* __restrict__ partQ)
{
    __shared__ float xs[64][16];
    __shared__ float ms[64][16];
    __shared__ float ws[2 * 16 * 128];
    __shared__ float aO[16][16];
    __shared__ float aD[16];
    __shared__ float red[2][1024];

    int tid = threadIdx.x;
    int tx = tid & 31, ty = tid >> 5;
    ((float*)aO)[tid] = attO[tid];
    if (tid < 16) aD[tid] = attD[tid];
    int nw = 2 * fin * 128;
    for (int i = tid; i < nw; i += 256) ws[i] = W[i];
    const float* w1s = ws + fin * 128;

    int rowBase = blockIdx.x * 64;
    int br = rowBase >> 17;                       // / 131072
    int local = rowBase - (br << 17);
    const float* xb =
        ((br == 0) ? x0 : (br == 1) ? x1p : (br == 2) ? x2p : x3p) + (long long)local * fin;

    for (int e = tid; e < 64 * fin; e += 256) {
        int r = e / fin, k = e - r * fin;
        xs[r][k] = xb[r * fin + k];
    }
    __syncthreads();
    for (int e = tid; e < 64 * fin; e += 256) {
        int r = e / fin, k = e - r * fin;
        int bl = r >> 4, ii = r & 15;
        float s = 0.f;
#pragma unroll
        for (int j = 0; j < 16; ++j) s += aO[ii][j] * xs[(bl << 4) + j][k];
        ms[r][k] = s;
    }
    __syncthreads();
    for (int e = tid; e < 64 * fin; e += 256) {
        int r = e / fin, k = e - r * fin;
        xs[r][k] *= aD[r & 15];
    }
    __syncthreads();

    float acc[8][4];
#pragma unroll
    for (int r = 0; r < 8; ++r) { acc[r][0]=0.f; acc[r][1]=0.f; acc[r][2]=0.f; acc[r][3]=0.f; }
    for (int k = 0; k < fin; ++k) {
        float4 w0 = *(const float4*)&ws[k * 128 + (tx << 2)];
        float4 w1 = *(const float4*)&w1s[k * 128 + (tx << 2)];
#pragma unroll
        for (int rr = 0; rr < 8; ++rr) {
            float xd = xs[(ty << 3) + rr][k];
            float xm = ms[(ty << 3) + rr][k];
            acc[rr][0] += xd * w0.x + xm * w1.x;
            acc[rr][1] += xd * w0.y + xm * w1.y;
            acc[rr][2] += xd * w0.z + xm * w1.z;
            acc[rr][3] += xd * w0.w + xm * w1.w;
        }
    }
#pragma unroll
    for (int rr = 0; rr < 8; ++rr) {
        long long row = rowBase + (ty << 3) + rr;
        float4 v = make_float4(acc[rr][0], acc[rr][1], acc[rr][2], acc[rr][3]);
        *(float4*)&y[row * HID + (tx << 2)] = v;
    }
    float ps[4] = {0.f,0.f,0.f,0.f}, pq[4] = {0.f,0.f,0.f,0.f};
#pragma unroll
    for (int rr = 0; rr < 8; ++rr)
#pragma unroll
        for (int c = 0; c < 4; ++c) { ps[c] += acc[rr][c]; pq[c] += acc[rr][c] * acc[rr][c]; }
#pragma unroll
    for (int c = 0; c < 4; ++c) {
        red[0][ty * 128 + (tx << 2) + c] = ps[c];
        red[1][ty * 128 + (tx << 2) + c] = pq[c];
    }
    __syncthreads();
    if (tid < 128) {
        float s = 0.f;
#pragma unroll
        for (int t = 0; t < 8; ++t) s += red[0][t * 128 + tid];
        partS[(long long)blockIdx.x * 128 + tid] = s;
    } else {
        int c = tid - 128;
        float q = 0.f;
#pragma unroll
        for (int t = 0; t < 8; ++t) q += red[1][t * 128 + c];
        partQ[(long long)blockIdx.x * 128 + c] = q;
    }
}

// ---------------- BN stats finalize: a = g*rsqrt(var+eps), b = beta - mu*a ----------------
__global__ void stats_kernel(const float* __restrict__ partS, const float* __restrict__ partQ,
                             const float* __restrict__ g, const float* __restrict__ beta,
                             float* __restrict__ ssA, float* __restrict__ ssB,
                             int nblkPerBranch)
{
    int br = blockIdx.x >> 7;
    int c = blockIdx.x & 127;
    long long base = (long long)br * nblkPerBranch * 128;
    double sd = 0.0, qd = 0.0;
    for (int b = threadIdx.x; b < nblkPerBranch; b += 256) {
        sd += partS[base + (long long)b * 128 + c];
        qd += partQ[base + (long long)b * 128 + c];
    }
    __shared__ double sS[256], sQ[256];
    sS[threadIdx.x] = sd; sQ[threadIdx.x] = qd;
    __syncthreads();
    for (int off = 128; off > 0; off >>= 1) {
        if (threadIdx.x < off) {
            sS[threadIdx.x] += sS[threadIdx.x + off];
            sQ[threadIdx.x] += sQ[threadIdx.x + off];
        }
        __syncthreads();
    }
    if (threadIdx.x == 0) {
        double invN = 1.0 / 131072.0;
        double mu = sS[0] * invN;
        double var = sQ[0] * invN - mu * mu;
        if (var < 0.0) var = 0.0;
        float a = g[c] * rsqrtf((float)var + EPSV);
        ssA[br * 128 + c] = a;
        ssB[br * 128 + c] = beta[c] - (float)mu * a;
    }
}

// ---------------- BN apply + ReLU (+ optional residual) ----------------
__global__ void apply_kernel(const float4* __restrict__ y, const float4* __restrict__ res,
                             float4* __restrict__ out,
                             const float* __restrict__ ssA, const float* __restrict__ ssB,
                             long long n4)
{
    long long i4 = (long long)blockIdx.x * 256 + threadIdx.x;
    if (i4 >= n4) return;
    int br = (int)(i4 >> 22);               // row = i4>>5, branch = row>>17
    int c4 = ((int)i4 & 31) << 2;
    float4 a = *(const float4*)&ssA[br * 128 + c4];
    float4 b = *(const float4*)&ssB[br * 128 + c4];
    float4 v = y[i4];
    float4 o;
    o.x = fmaxf(fmaf(a.x, v.x, b.x), 0.f);
    o.y = fmaxf(fmaf(a.y, v.y, b.y), 0.f);
    o.z = fmaxf(fmaf(a.z, v.z, b.z), 0.f);
    o.w = fmaxf(fmaf(a.w, v.w, b.w), 0.f);
    if (res) {
        float4 rv = res[i4];
        o.x += rv.x; o.y += rv.y; o.z += rv.z; o.w += rv.w;
    }
    out[i4] = o;
}

// ---------------- output conv 128 -> 3 (with bias, no BN) ----------------
__global__ __launch_bounds__(256) void outconv_kernel(
    const float* __restrict__ x,
    const float* __restrict__ Wout,    // [5][2][128][3]
    const float* __restrict__ bout,    // [5][3]
    const float* __restrict__ attO,    // base at layer 10
    const float* __restrict__ attD,    // base at layer 10
    float* __restrict__ dout,          // may be nullptr (branch mode, partial out)
    float* __restrict__ merged,
    int catMode)
{
    __shared__ float xs[256][36];
    __shared__ float wflat[768];
    __shared__ float aO[16][16];
    __shared__ float aD[16];

    int tid = threadIdx.x;
    int rowBase = blockIdx.x * 256;
    int br = catMode ? 4 : (rowBase >> 17);
    int widx = br;
    const float* aOp = attO + br * 256;
    ((float*)aO)[tid] = aOp[tid];
    if (tid < 16) aD[tid] = attD[br * 16 + tid];
    for (int i = tid; i < 768; i += 256) wflat[i] = Wout[widx * 768 + i];
    int local = catMode ? rowBase : rowBase - (br << 17);

    int r = tid;
    int ii = r & 15, bl = r >> 4;
    float acc[3] = {0.f, 0.f, 0.f};

    for (int kt = 0; kt < 4; ++kt) {
        int k0 = kt * 32;
        for (int idx = tid; idx < 2048; idx += 256) {
            int rr = idx >> 3, c4 = (idx & 7) << 2;
            *(float4*)&xs[rr][c4] =
                *(const float4*)&x[(long long)(rowBase + rr) * HID + k0 + c4];
        }
        __syncthreads();
        float aDv = aD[ii];
#pragma unroll 4
        for (int k = 0; k < 32; ++k) {
            float xm = 0.f;
#pragma unroll
            for (int jj = 0; jj < 16; ++jj) xm += aO[ii][jj] * xs[(bl << 4) + jj][k];
            float xd = aDv * xs[r][k];
            int kg = k0 + k;
            acc[0] += xd * wflat[kg * 3 + 0] + xm * wflat[384 + kg * 3 + 0];
            acc[1] += xd * wflat[kg * 3 + 1] + xm * wflat[384 + kg * 3 + 1];
            acc[2] += xd * wflat[kg * 3 + 2] + xm * wflat[384 + kg * 3 + 2];
        }
        __syncthreads();
    }
    float o0 = acc[0] + bout[widx * 3 + 0];
    float o1 = acc[1] + bout[widx * 3 + 1];
    float o2 = acc[2] + bout[widx * 3 + 2];
    long long grow = local + r;
    if (dout) {
        float* op = dout + (catMode ? 0 : (long long)(1 + br) * ROWSB * 3);
        op[grow * 3 + 0] = o0;
        op[grow * 3 + 1] = o1;
        op[grow * 3 + 2] = o2;
    }
    if (!catMode) {
        merged[grow * 12 + br * 3 + 0] = o0;
        merged[grow * 12 + br * 3 + 1] = o1;
        merged[grow * 12 + br * 3 + 2] = o2;
    }
}

// ---------------- host orchestration ----------------
extern "C" void kernel_launch(void* const* d_in, const int* in_sizes, int n_in,
                              void* d_out, int out_size)
{
    const float* x1 = (const float*)d_in[0];
    const float* x2 = (const float*)d_in[1];
    const float* x3 = (const float*)d_in[2];
    const float* x4 = (const float*)d_in[3];
    const float* W_in = (const float*)d_in[4];
    const float* e_in = (const float*)d_in[6];
    const float* g_in = (const float*)d_in[7];
    const float* beta_in = (const float*)d_in[8];
    const float* W_cat = (const float*)d_in[9];
    const float* e_cat = (const float*)d_in[11];
    const float* g_cat = (const float*)d_in[12];
    const float* beta_cat = (const float*)d_in[13];
    const float* W_res = (const float*)d_in[14];
    const float* e_res = (const float*)d_in[16];
    const float* g_res = (const float*)d_in[17];
    const float* beta_res = (const float*)d_in[18];
    const float* W_out = (const float*)d_in[19];
    const float* b_out = (const float*)d_in[20];
    const float* e_out = (const float*)d_in[21];
    float* out = (float*)d_out;

    float *bufA, *bufB, *bufC, *merged, *partS, *partQ, *ssA, *ssB, *attO, *attD;
    cudaGetSymbolAddress((void**)&bufA, g_bufA);
    cudaGetSymbolAddress((void**)&bufB, g_bufB);
    cudaGetSymbolAddress((void**)&bufC, g_bufC);
    cudaGetSymbolAddress((void**)&merged, g_merged);
    cudaGetSymbolAddress((void**)&partS, g_partS);
    cudaGetSymbolAddress((void**)&partQ, g_partQ);
    cudaGetSymbolAddress((void**)&ssA, g_ssA);
    cudaGetSymbolAddress((void**)&ssB, g_ssB);
    cudaGetSymbolAddress((void**)&attO, g_attO);
    cudaGetSymbolAddress((void**)&attD, g_attD);

    const int SEG = ROWSB * 3;                  // 393216 floats per output tensor
    float* doutBranch = (out_size >= 5 * SEG) ? out : nullptr;

    att_kernel<<<15, 16>>>(e_in, e_cat, e_res, e_out, attO, attD);

    // ===== 4-branch phase (batched, rows = 4*131072; shared weights) =====
    const long long N4b = (long long)4 * ROWSB * 32;   // float4 count
    gconv_small_kernel<<<8192, 256>>>(x1, x2, x3, x4, 2, W_in, attO, attD,
                                      bufB, partS, partQ);
    stats_kernel<<<512, 256>>>(partS, partQ, g_in, beta_in, ssA, ssB, 2048);
    apply_kernel<<<65536, 256>>>((const float4*)bufB, nullptr, (float4*)bufA, ssA, ssB, N4b);

    for (int l = 0; l < 4; ++l) {
        const float* Wa = W_res + (2 * l) * 32768;
        const float* Wb = W_res + (2 * l + 1) * 32768;
        gconv128_kernel<<<8192, 256>>>(bufA, bufB, Wa,
                                       attO + (2 + 2 * l) * 256, attD + (2 + 2 * l) * 16,
                                       partS, partQ);
        stats_kernel<<<512, 256>>>(partS, partQ, g_res + (2 * l) * 128,
                                   beta_res + (2 * l) * 128, ssA, ssB, 2048);
        apply_kernel<<<65536, 256>>>((const float4*)bufB, nullptr, (float4*)bufB, ssA, ssB, N4b);
        gconv128_kernel<<<8192, 256>>>(bufB, bufC, Wb,
                                       attO + (3 + 2 * l) * 256, attD + (3 + 2 * l) * 16,
                                       partS, partQ);
        stats_kernel<<<512, 256>>>(partS, partQ, g_res + (2 * l + 1) * 128,
                                   beta_res + (2 * l + 1) * 128, ssA, ssB, 2048);
        apply_kernel<<<65536, 256>>>((const float4*)bufC, (const float4*)bufA,
                                     (float4*)bufA, ssA, ssB, N4b);
    }
    outconv_kernel<<<2048, 256>>>(bufA, W_out, b_out, attO + 10 * 256, attD + 10 * 16,
                                  doutBranch, merged, 0);

    // ===== concat phase (rows = 131072) =====
    const long long N4c = (long long)ROWSB * 32;
    gconv_small_kernel<<<2048, 256>>>(merged, merged, merged, merged, 12, W_cat,
                                      attO + 256, attD + 16, bufB, partS, partQ);
    stats_kernel<<<128, 256>>>(partS, partQ, g_cat, beta_cat, ssA, ssB, 2048);
    apply_kernel<<<16384, 256>>>((const float4*)bufB, nullptr, (float4*)bufA, ssA, ssB, N4c);

    for (int l = 0; l < 4; ++l) {
        const float* Wa = W_res + (2 * l) * 32768;
        const float* Wb = W_res + (2 * l + 1) * 32768;
        gconv128_kernel<<<2048, 256>>>(bufA, bufB, Wa,
                                       attO + (2 + 2 * l) * 256, attD + (2 + 2 * l) * 16,
                                       partS, partQ);
        stats_kernel<<<128, 256>>>(partS, partQ, g_res + (2 * l) * 128,
                                   beta_res + (2 * l) * 128, ssA, ssB, 2048);
        apply_kernel<<<16384, 256>>>((const float4*)bufB, nullptr, (float4*)bufB, ssA, ssB, N4c);
        gconv128_kernel<<<2048, 256>>>(bufB, bufC, Wb,
                                       attO + (3 + 2 * l) * 256, attD + (3 + 2 * l) * 16,
                                       partS, partQ);
        stats_kernel<<<128, 256>>>(partS, partQ, g_res + (2 * l + 1) * 128,
                                   beta_res + (2 * l + 1) * 128, ssA, ssB, 2048);
        apply_kernel<<<16384, 256>>>((const float4*)bufC, (const float4*)bufA,
                                     (float4*)bufA, ssA, ssB, N4c);
    }
    outconv_kernel<<<512, 256>>>(bufA, W_out, b_out, attO + 10 * 256, attD + 10 * 16,
                                 out, merged, 1);
}

// round 6
// speedup vs baseline: 1.0014x; 1.0014x over previous
#include <cuda_runtime.h>
#include <math.h>

#define J 16
#define HID 128
#define ROWSB 131072            // 8192*16 rows per branch
#define EPSV 1e-5f

// ---------------- static device scratch (no runtime allocation) ----------------
__device__ float g_bufA[4 * ROWSB * HID];   // 256 MB
__device__ float g_bufB[4 * ROWSB * HID];   // 256 MB
__device__ float g_bufC[4 * ROWSB * HID];   // 256 MB
__device__ float g_merged[ROWSB * 12];
__device__ float g_partS[8192 * 128];
__device__ float g_partQ[8192 * 128];
__device__ float g_ssA[4 * 128];
__device__ float g_ssB[4 * 128];
__device__ float g_attO[15 * 256];          // softmax att, diag zeroed
__device__ float g_attD[15 * 16];           // softmax att diagonal

// Hardcoded H3.6M 16-joint adjacency (incl. self-loops), bit j of row i
__constant__ unsigned short MASKROW[16] = {
    0x0093, 0x0007, 0x000E, 0x000C, 0x0031, 0x0070, 0x0060, 0x0181,
    0x4B80, 0x0700, 0x0600, 0x1900, 0x3800, 0x3000, 0xC100, 0xC000};

// ---------------- attention softmax (15 layers x 16 rows) ----------------
__global__ void att_kernel(const float* __restrict__ e_in,
                           const float* __restrict__ e_cat,
                           const float* __restrict__ e_res,
                           const float* __restrict__ e_out,
                           float* __restrict__ attO, float* __restrict__ attD)
{
    int layer = blockIdx.x;      // 0=in, 1=cat, 2..9=res, 10..14=out
    int row = threadIdx.x;       // 16 threads
    const float* e;
    if (layer == 0)      e = e_in;
    else if (layer == 1) e = e_cat;
    else if (layer < 10) e = e_res + (layer - 2) * 256;
    else                 e = e_out + (layer - 10) * 256;

    unsigned m = MASKROW[row];
    float mx = -1e30f;
    for (int j = 0; j < 16; ++j)
        if ((m >> j) & 1) mx = fmaxf(mx, e[row * 16 + j]);
    float ex[16];
    float sum = 0.f;
    for (int j = 0; j < 16; ++j) {
        float v = ((m >> j) & 1) ? expf(e[row * 16 + j] - mx) : 0.f;
        ex[j] = v; sum += v;
    }
    float inv = 1.f / sum;
    for (int j = 0; j < 16; ++j)
        attO[layer * 256 + row * 16 + j] = (j == row) ? 0.f : ex[j] * inv;
    attD[layer * 16 + row] = ex[row] * inv;
}

// ---------------- main 128->128 graph conv (the hot kernel) ----------------
// Block: 64 rows (4 batches x 16 joints) x 128 cols, 256 threads, BK=16.
__global__ __launch_bounds__(256) void gconv128_kernel(
    const float* __restrict__ x, float* __restrict__ y,
    const float* __restrict__ W,        // [2][128][128]
    const float* __restrict__ attO, const float* __restrict__ attD,
    float* __restrict__ partS, float* __restrict__ partQ)
{
    __shared__ float xs[64][16];
    __shared__ float ms[64][16];
    __shared__ float w0s[16][128];
    __shared__ float w1s[16][128];
    __shared__ float aO[16][16];
    __shared__ float aD[16];

    int tid = threadIdx.x;
    int tx = tid & 31, ty = tid >> 5;
    ((float*)aO)[tid] = attO[tid];
    if (tid < 16) aD[tid] = attD[tid];

    int rowBase = blockIdx.x * 64;
    const float* xb = x + (long long)rowBase * HID;

    float acc[8][4];
#pragma unroll
    for (int r = 0; r < 8; ++r) { acc[r][0]=0.f; acc[r][1]=0.f; acc[r][2]=0.f; acc[r][3]=0.f; }

    for (int kt = 0; kt < 8; ++kt) {
        int k0 = kt * 16;
        // W tiles: 2 x 16x128 floats = 512 float4 per matrix
#pragma unroll
        for (int i = tid; i < 512; i += 256) {
            int kk = i >> 5, c4 = (i & 31) << 2;
            *(float4*)&w0s[kk][c4] = *(const float4*)&W[(k0 + kk) * HID + c4];
            *(float4*)&w1s[kk][c4] = *(const float4*)&W[16384 + (k0 + kk) * HID + c4];
        }
        // x tile: 64x16 floats = 256 float4
        {
            int r = tid >> 2, c4 = (tid & 3) << 2;
            *(float4*)&xs[r][c4] = *(const float4*)&xb[r * HID + k0 + c4];
        }
        __syncthreads();
        // mixed tile m[b,i,k] = sum_j attO[i][j] * x[b,j,k]
#pragma unroll
        for (int e = tid; e < 1024; e += 256) {
            int r = e >> 4, k = e & 15;
            int bl = r >> 4, ii = r & 15;
            float s = 0.f;
#pragma unroll
            for (int j = 0; j < 16; ++j) s += aO[ii][j] * xs[(bl << 4) + j][k];
            ms[r][k] = s;
        }
        __syncthreads();
        // diag scale in place
#pragma unroll
        for (int e = tid; e < 1024; e += 256) {
            int r = e >> 4, k = e & 15;
            xs[r][k] *= aD[r & 15];
        }
        __syncthreads();
#pragma unroll
        for (int k = 0; k < 16; ++k) {
            float4 w0 = *(float4*)&w0s[k][tx << 2];
            float4 w1 = *(float4*)&w1s[k][tx << 2];
#pragma unroll
            for (int rr = 0; rr < 8; ++rr) {
                float xd = xs[(ty << 3) + rr][k];
                float xm = ms[(ty << 3) + rr][k];
                acc[rr][0] += xd * w0.x + xm * w1.x;
                acc[rr][1] += xd * w0.y + xm * w1.y;
                acc[rr][2] += xd * w0.z + xm * w1.z;
                acc[rr][3] += xd * w0.w + xm * w1.w;
            }
        }
        __syncthreads();
    }
    // write y (no bias: it cancels in the following BatchNorm)
#pragma unroll
    for (int rr = 0; rr < 8; ++rr) {
        long long row = rowBase + (ty << 3) + rr;
        float4 v = make_float4(acc[rr][0], acc[rr][1], acc[rr][2], acc[rr][3]);
        *(float4*)&y[row * HID + (tx << 2)] = v;
    }
    // per-block BN partials (deterministic, no atomics)
    float ps[4] = {0.f,0.f,0.f,0.f}, pq[4] = {0.f,0.f,0.f,0.f};
#pragma unroll
    for (int rr = 0; rr < 8; ++rr)
#pragma unroll
        for (int c = 0; c < 4; ++c) { ps[c] += acc[rr][c]; pq[c] += acc[rr][c] * acc[rr][c]; }
    float* redS = &xs[0][0];   // 1024 floats
    float* redQ = &ms[0][0];   // 1024 floats
#pragma unroll
    for (int c = 0; c < 4; ++c) {
        redS[ty * 128 + (tx << 2) + c] = ps[c];
        redQ[ty * 128 + (tx << 2) + c] = pq[c];
    }
    __syncthreads();
    if (tid < 128) {
        float s = 0.f;
#pragma unroll
        for (int t = 0; t < 8; ++t) s += redS[t * 128 + tid];
        partS[(long long)blockIdx.x * 128 + tid] = s;
    } else {
        int c = tid - 128;
        float q = 0.f;
#pragma unroll
        for (int t = 0; t < 8; ++t) q += redQ[t * 128 + c];
        partQ[(long long)blockIdx.x * 128 + c] = q;
    }
}

// ---------------- small-Fin graph conv (Fin=2 input, Fin=12 cat) ----------------
__global__ __launch_bounds__(256) void gconv_small_kernel(
    const float* __restrict__ x0, const float* __restrict__ x1p,
    const float* __restrict__ x2p, const float* __restrict__ x3p,
    int fin,
    const float* __restrict__ W,        // [2][fin][128]
    const float* __restrict__ attO, const float* __restrict__ attD,
    float* __restrict__ y, float* __restrict__ partS, float* __restrict__ partQ)
{
    __shared__ float xs[64][16];
    __shared__ float ms[64][16];
    __shared__ float ws[2 * 16 * 128];
    __shared__ float aO[16][16];
    __shared__ float aD[16];
    __shared__ float red[2][1024];

    int tid = threadIdx.x;
    int tx = tid & 31, ty = tid >> 5;
    ((float*)aO)[tid] = attO[tid];
    if (tid < 16) aD[tid] = attD[tid];
    int nw = 2 * fin * 128;
    for (int i = tid; i < nw; i += 256) ws[i] = W[i];
    const float* w1s = ws + fin * 128;

    int rowBase = blockIdx.x * 64;
    int br = rowBase >> 17;                       // / 131072
    int local = rowBase - (br << 17);
    const float* xb =
        ((br == 0) ? x0 : (br == 1) ? x1p : (br == 2) ? x2p : x3p) + (long long)local * fin;

    for (int e = tid; e < 64 * fin; e += 256) {
        int r = e / fin, k = e - r * fin;
        xs[r][k] = xb[r * fin + k];
    }
    __syncthreads();
    for (int e = tid; e < 64 * fin; e += 256) {
        int r = e / fin, k = e - r * fin;
        int bl = r >> 4, ii = r & 15;
        float s = 0.f;
#pragma unroll
        for (int j = 0; j < 16; ++j) s += aO[ii][j] * xs[(bl << 4) + j][k];
        ms[r][k] = s;
    }
    __syncthreads();
    for (int e = tid; e < 64 * fin; e += 256) {
        int r = e / fin, k = e - r * fin;
        xs[r][k] *= aD[r & 15];
    }
    __syncthreads();

    float acc[8][4];
#pragma unroll
    for (int r = 0; r < 8; ++r) { acc[r][0]=0.f; acc[r][1]=0.f; acc[r][2]=0.f; acc[r][3]=0.f; }
    for (int k = 0; k < fin; ++k) {
        float4 w0 = *(const float4*)&ws[k * 128 + (tx << 2)];
        float4 w1 = *(const float4*)&w1s[k * 128 + (tx << 2)];
#pragma unroll
        for (int rr = 0; rr < 8; ++rr) {
            float xd = xs[(ty << 3) + rr][k];
            float xm = ms[(ty << 3) + rr][k];
            acc[rr][0] += xd * w0.x + xm * w1.x;
            acc[rr][1] += xd * w0.y + xm * w1.y;
            acc[rr][2] += xd * w0.z + xm * w1.z;
            acc[rr][3] += xd * w0.w + xm * w1.w;
        }
    }
#pragma unroll
    for (int rr = 0; rr < 8; ++rr) {
        long long row = rowBase + (ty << 3) + rr;
        float4 v = make_float4(acc[rr][0], acc[rr][1], acc[rr][2], acc[rr][3]);
        *(float4*)&y[row * HID + (tx << 2)] = v;
    }
    float ps[4] = {0.f,0.f,0.f,0.f}, pq[4] = {0.f,0.f,0.f,0.f};
#pragma unroll
    for (int rr = 0; rr < 8; ++rr)
#pragma unroll
        for (int c = 0; c < 4; ++c) { ps[c] += acc[rr][c]; pq[c] += acc[rr][c] * acc[rr][c]; }
#pragma unroll
    for (int c = 0; c < 4; ++c) {
        red[0][ty * 128 + (tx << 2) + c] = ps[c];
        red[1][ty * 128 + (tx << 2) + c] = pq[c];
    }
    __syncthreads();
    if (tid < 128) {
        float s = 0.f;
#pragma unroll
        for (int t = 0; t < 8; ++t) s += red[0][t * 128 + tid];
        partS[(long long)blockIdx.x * 128 + tid] = s;
    } else {
        int c = tid - 128;
        float q = 0.f;
#pragma unroll
        for (int t = 0; t < 8; ++t) q += red[1][t * 128 + c];
        partQ[(long long)blockIdx.x * 128 + c] = q;
    }
}

// ---------------- BN stats finalize: a = g*rsqrt(var+eps), b = beta - mu*a ----------------
__global__ void stats_kernel(const float* __restrict__ partS, const float* __restrict__ partQ,
                             const float* __restrict__ g, const float* __restrict__ beta,
                             float* __restrict__ ssA, float* __restrict__ ssB,
                             int nblkPerBranch)
{
    int br = blockIdx.x >> 7;
    int c = blockIdx.x & 127;
    long long base = (long long)br * nblkPerBranch * 128;
    double sd = 0.0, qd = 0.0;
    for (int b = threadIdx.x; b < nblkPerBranch; b += 256) {
        sd += partS[base + (long long)b * 128 + c];
        qd += partQ[base + (long long)b * 128 + c];
    }
    __shared__ double sS[256], sQ[256];
    sS[threadIdx.x] = sd; sQ[threadIdx.x] = qd;
    __syncthreads();
    for (int off = 128; off > 0; off >>= 1) {
        if (threadIdx.x < off) {
            sS[threadIdx.x] += sS[threadIdx.x + off];
            sQ[threadIdx.x] += sQ[threadIdx.x + off];
        }
        __syncthreads();
    }
    if (threadIdx.x == 0) {
        double invN = 1.0 / 131072.0;
        double mu = sS[0] * invN;
        double var = sQ[0] * invN - mu * mu;
        if (var < 0.0) var = 0.0;
        float a = g[c] * rsqrtf((float)var + EPSV);
        ssA[br * 128 + c] = a;
        ssB[br * 128 + c] = beta[c] - (float)mu * a;
    }
}

// ---------------- BN apply + ReLU (+ optional residual) ----------------
__global__ void apply_kernel(const float4* __restrict__ y, const float4* __restrict__ res,
                             float4* __restrict__ out,
                             const float* __restrict__ ssA, const float* __restrict__ ssB,
                             long long n4)
{
    long long i4 = (long long)blockIdx.x * 256 + threadIdx.x;
    if (i4 >= n4) return;
    int br = (int)(i4 >> 22);               // row = i4>>5, branch = row>>17
    int c4 = ((int)i4 & 31) << 2;
    float4 a = *(const float4*)&ssA[br * 128 + c4];
    float4 b = *(const float4*)&ssB[br * 128 + c4];
    float4 v = y[i4];
    float4 o;
    o.x = fmaxf(fmaf(a.x, v.x, b.x), 0.f);
    o.y = fmaxf(fmaf(a.y, v.y, b.y), 0.f);
    o.z = fmaxf(fmaf(a.z, v.z, b.z), 0.f);
    o.w = fmaxf(fmaf(a.w, v.w, b.w), 0.f);
    if (res) {
        float4 rv = res[i4];
        o.x += rv.x; o.y += rv.y; o.z += rv.z; o.w += rv.w;
    }
    out[i4] = o;
}

// ---------------- output conv 128 -> 3 (with bias, no BN) ----------------
__global__ __launch_bounds__(256) void outconv_kernel(
    const float* __restrict__ x,
    const float* __restrict__ Wout,    // [5][2][128][3]
    const float* __restrict__ bout,    // [5][3]
    const float* __restrict__ attO,    // base at layer 10
    const float* __restrict__ attD,    // base at layer 10
    float* __restrict__ dout,          // may be nullptr (branch mode, partial out)
    float* __restrict__ merged,
    int catMode)
{
    __shared__ float xs[256][36];
    __shared__ float wflat[768];
    __shared__ float aO[16][16];
    __shared__ float aD[16];

    int tid = threadIdx.x;
    int rowBase = blockIdx.x * 256;
    int br = catMode ? 4 : (rowBase >> 17);
    int widx = br;
    const float* aOp = attO + br * 256;
    ((float*)aO)[tid] = aOp[tid];
    if (tid < 16) aD[tid] = attD[br * 16 + tid];
    for (int i = tid; i < 768; i += 256) wflat[i] = Wout[widx * 768 + i];
    int local = catMode ? rowBase : rowBase - (br << 17);

    int r = tid;
    int ii = r & 15, bl = r >> 4;
    float acc[3] = {0.f, 0.f, 0.f};

    for (int kt = 0; kt < 4; ++kt) {
        int k0 = kt * 32;
        for (int idx = tid; idx < 2048; idx += 256) {
            int rr = idx >> 3, c4 = (idx & 7) << 2;
            *(float4*)&xs[rr][c4] =
                *(const float4*)&x[(long long)(rowBase + rr) * HID + k0 + c4];
        }
        __syncthreads();
        float aDv = aD[ii];
#pragma unroll 4
        for (int k = 0; k < 32; ++k) {
            float xm = 0.f;
#pragma unroll
            for (int jj = 0; jj < 16; ++jj) xm += aO[ii][jj] * xs[(bl << 4) + jj][k];
            float xd = aDv * xs[r][k];
            int kg = k0 + k;
            acc[0] += xd * wflat[kg * 3 + 0] + xm * wflat[384 + kg * 3 + 0];
            acc[1] += xd * wflat[kg * 3 + 1] + xm * wflat[384 + kg * 3 + 1];
            acc[2] += xd * wflat[kg * 3 + 2] + xm * wflat[384 + kg * 3 + 2];
        }
        __syncthreads();
    }
    float o0 = acc[0] + bout[widx * 3 + 0];
    float o1 = acc[1] + bout[widx * 3 + 1];
    float o2 = acc[2] + bout[widx * 3 + 2];
    long long grow = local + r;
    if (dout) {
        float* op = dout + (catMode ? 0 : (long long)(1 + br) * ROWSB * 3);
        op[grow * 3 + 0] = o0;
        op[grow * 3 + 1] = o1;
        op[grow * 3 + 2] = o2;
    }
    if (!catMode) {
        merged[grow * 12 + br * 3 + 0] = o0;
        merged[grow * 12 + br * 3 + 1] = o1;
        merged[grow * 12 + br * 3 + 2] = o2;
    }
}

// ---------------- host orchestration ----------------
extern "C" void kernel_launch(void* const* d_in, const int* in_sizes, int n_in,
                              void* d_out, int out_size)
{
    const float* x1 = (const float*)d_in[0];
    const float* x2 = (const float*)d_in[1];
    const float* x3 = (const float*)d_in[2];
    const float* x4 = (const float*)d_in[3];
    const float* W_in = (const float*)d_in[4];
    const float* e_in = (const float*)d_in[6];
    const float* g_in = (const float*)d_in[7];
    const float* beta_in = (const float*)d_in[8];
    const float* W_cat = (const float*)d_in[9];
    const float* e_cat = (const float*)d_in[11];
    const float* g_cat = (const float*)d_in[12];
    const float* beta_cat = (const float*)d_in[13];
    const float* W_res = (const float*)d_in[14];
    const float* e_res = (const float*)d_in[16];
    const float* g_res = (const float*)d_in[17];
    const float* beta_res = (const float*)d_in[18];
    const float* W_out = (const float*)d_in[19];
    const float* b_out = (const float*)d_in[20];
    const float* e_out = (const float*)d_in[21];
    float* out = (float*)d_out;

    float *bufA, *bufB, *bufC, *merged, *partS, *partQ, *ssA, *ssB, *attO, *attD;
    cudaGetSymbolAddress((void**)&bufA, g_bufA);
    cudaGetSymbolAddress((void**)&bufB, g_bufB);
    cudaGetSymbolAddress((void**)&bufC, g_bufC);
    cudaGetSymbolAddress((void**)&merged, g_merged);
    cudaGetSymbolAddress((void**)&partS, g_partS);
    cudaGetSymbolAddress((void**)&partQ, g_partQ);
    cudaGetSymbolAddress((void**)&ssA, g_ssA);
    cudaGetSymbolAddress((void**)&ssB, g_ssB);
    cudaGetSymbolAddress((void**)&attO, g_attO);
    cudaGetSymbolAddress((void**)&attD, g_attD);

    const int SEG = ROWSB * 3;                  // 393216 floats per output tensor
    float* doutBranch = (out_size >= 5 * SEG) ? out : nullptr;

    att_kernel<<<15, 16>>>(e_in, e_cat, e_res, e_out, attO, attD);

    // ===== 4-branch phase (batched, rows = 4*131072; shared weights) =====
    const long long N4b = (long long)4 * ROWSB * 32;   // float4 count
    gconv_small_kernel<<<8192, 256>>>(x1, x2, x3, x4, 2, W_in, attO, attD,
                                      bufB, partS, partQ);
    stats_kernel<<<512, 256>>>(partS, partQ, g_in, beta_in, ssA, ssB, 2048);
    apply_kernel<<<65536, 256>>>((const float4*)bufB, nullptr, (float4*)bufA, ssA, ssB, N4b);

    for (int l = 0; l < 4; ++l) {
        const float* Wa = W_res + (2 * l) * 32768;
        const float* Wb = W_res + (2 * l + 1) * 32768;
        gconv128_kernel<<<8192, 256>>>(bufA, bufB, Wa,
                                       attO + (2 + 2 * l) * 256, attD + (2 + 2 * l) * 16,
                                       partS, partQ);
        stats_kernel<<<512, 256>>>(partS, partQ, g_res + (2 * l) * 128,
                                   beta_res + (2 * l) * 128, ssA, ssB, 2048);
        apply_kernel<<<65536, 256>>>((const float4*)bufB, nullptr, (float4*)bufB, ssA, ssB, N4b);
        gconv128_kernel<<<8192, 256>>>(bufB, bufC, Wb,
                                       attO + (3 + 2 * l) * 256, attD + (3 + 2 * l) * 16,
                                       partS, partQ);
        stats_kernel<<<512, 256>>>(partS, partQ, g_res + (2 * l + 1) * 128,
                                   beta_res + (2 * l + 1) * 128, ssA, ssB, 2048);
        apply_kernel<<<65536, 256>>>((const float4*)bufC, (const float4*)bufA,
                                     (float4*)bufA, ssA, ssB, N4b);
    }
    outconv_kernel<<<2048, 256>>>(bufA, W_out, b_out, attO + 10 * 256, attD + 10 * 16,
                                  doutBranch, merged, 0);

    // ===== concat phase (rows = 131072) =====
    const long long N4c = (long long)ROWSB * 32;
    gconv_small_kernel<<<2048, 256>>>(merged, merged, merged, merged, 12, W_cat,
                                      attO + 256, attD + 16, bufB, partS, partQ);
    stats_kernel<<<128, 256>>>(partS, partQ, g_cat, beta_cat, ssA, ssB, 2048);
    apply_kernel<<<16384, 256>>>((const float4*)bufB, nullptr, (float4*)bufA, ssA, ssB, N4c);

    for (int l = 0; l < 4; ++l) {
        const float* Wa = W_res + (2 * l) * 32768;
        const float* Wb = W_res + (2 * l + 1) * 32768;
        gconv128_kernel<<<2048, 256>>>(bufA, bufB, Wa,
                                       attO + (2 + 2 * l) * 256, attD + (2 + 2 * l) * 16,
                                       partS, partQ);
        stats_kernel<<<128, 256>>>(partS, partQ, g_res + (2 * l) * 128,
                                   beta_res + (2 * l) * 128, ssA, ssB, 2048);
        apply_kernel<<<16384, 256>>>((const float4*)bufB, nullptr, (float4*)bufB, ssA, ssB, N4c);
        gconv128_kernel<<<2048, 256>>>(bufB, bufC, Wb,
                                       attO + (3 + 2 * l) * 256, attD + (3 + 2 * l) * 16,
                                       partS, partQ);
        stats_kernel<<<128, 256>>>(partS, partQ, g_res + (2 * l + 1) * 128,
                                   beta_res + (2 * l + 1) * 128, ssA, ssB, 2048);
        apply_kernel<<<16384, 256>>>((const float4*)bufC, (const float4*)bufA,
                                     (float4*)bufA, ssA, ssB, N4c);
    }
    outconv_kernel<<<512, 256>>>(bufA, W_out, b_out, attO + 10 * 256, attD + 10 * 16,
                                 out, merged, 1);
}